// round 5
// baseline (speedup 1.0000x reference)
#include <cuda_runtime.h>
#include <math.h>

#define BATCH 4
#define SQL 2048
#define SKL 2048
#define DM 1024
#define NH 16
#define HD 64

// Scratch (module-load allocation, allowed): projected Q/K in [b][h][d][s], V in [b][s][n]
__device__ float g_Q[(size_t)BATCH * NH * HD * SQL];
__device__ float g_K[(size_t)BATCH * NH * HD * SKL];
__device__ float g_V[(size_t)BATCH * SKL * DM];

// ---------------------------------------------------------------------------
// Projection GEMM: Y[m][n] = X[m][:] . W[:][n],  M = B*S = 8192, N = K = 1024
// Tile 64x64, BK=16, 256 threads, 4x4 per-thread micro-tile.
// mode 0 -> g_Q transposed [b][h][d][s]
// mode 1 -> g_K transposed [b][h][d][s]
// mode 2 -> g_V natural    [b*s][n]
// ---------------------------------------------------------------------------
__global__ __launch_bounds__(256) void proj_kernel(const float* __restrict__ X,
                                                   const float* __restrict__ W,
                                                   int mode)
{
    __shared__ float sm[64 * 68];
    float (*Xs)[68] = (float(*)[68])sm;             // [16][68], Xs[k][m]
    float (*Ws)[68] = (float(*)[68])(sm + 16 * 68); // [16][68], Ws[k][n]

    const int tid = threadIdx.x;
    const int tx = tid & 15, ty = tid >> 4;
    const int m0 = blockIdx.x * 64;
    const int h  = blockIdx.y;          // 64-wide n-tile == one head
    const int n0 = h * 64;
    const int lr = tid >> 2;            // X tile row 0..63
    const int lk = (tid & 3) * 4;       // X tile k  0,4,8,12
    const int wr = ty;                  // W tile row 0..15
    const int wc = tx * 4;

    float acc[4][4];
#pragma unroll
    for (int i = 0; i < 4; i++)
#pragma unroll
        for (int j = 0; j < 4; j++) acc[i][j] = 0.f;

    for (int k0 = 0; k0 < DM; k0 += 16) {
        float4 xv = *(const float4*)&X[(size_t)(m0 + lr) * DM + k0 + lk];
        float4 wv = *(const float4*)&W[(size_t)(k0 + wr) * DM + n0 + wc];
        __syncthreads();
        Xs[lk + 0][lr] = xv.x;
        Xs[lk + 1][lr] = xv.y;
        Xs[lk + 2][lr] = xv.z;
        Xs[lk + 3][lr] = xv.w;
        *(float4*)&Ws[wr][wc] = wv;
        __syncthreads();
#pragma unroll
        for (int kk = 0; kk < 16; kk++) {
            float4 a4 = *(const float4*)&Xs[kk][ty * 4];
            float4 b4 = *(const float4*)&Ws[kk][tx * 4];
            float a[4] = {a4.x, a4.y, a4.z, a4.w};
            float b[4] = {b4.x, b4.y, b4.z, b4.w};
#pragma unroll
            for (int i = 0; i < 4; i++)
#pragma unroll
                for (int j = 0; j < 4; j++)
                    acc[i][j] = fmaf(a[i], b[j], acc[i][j]);
        }
    }

    const int bb = m0 >> 11;       // m0 / 2048 (S divides tile grid exactly)
    const int s0 = m0 & 2047;

    if (mode == 2) {
#pragma unroll
        for (int i = 0; i < 4; i++) {
            float4 o = make_float4(acc[i][0], acc[i][1], acc[i][2], acc[i][3]);
            *(float4*)&g_V[(size_t)(m0 + ty * 4 + i) * DM + n0 + tx * 4] = o;
        }
    } else {
        float* out = (mode == 0) ? g_Q : g_K;
        __syncthreads();
        float (*St)[68] = (float(*)[68])sm;  // [64][68] staging for transpose
#pragma unroll
        for (int i = 0; i < 4; i++)
#pragma unroll
            for (int j = 0; j < 4; j++)
                St[tx * 4 + j][ty * 4 + i] = acc[i][j];
        __syncthreads();
        const size_t base = ((size_t)(bb * NH + h) * HD) * SQL + s0;
        for (int idx = tid; idx < 64 * 64; idx += 256) {
            int dl = idx >> 6, sl = idx & 63;
            out[base + (size_t)dl * SQL + sl] = St[dl][sl];
        }
    }
}

// ---------------------------------------------------------------------------
// Flash attention. CTA: 64 q-rows x one (b,h). Loops over 32 k-tiles of 64.
// Thread (ty,tx) owns q-rows ty*4..+3; S cols / O d-cols tx*4..+3.
// Row reductions via shfl_xor over the 16-lane tx group.
// Ps (exp(S-m)) reuses Ks buffer. Dyn smem = 3 * 64*68 * 4B = 52224 B.
// ---------------------------------------------------------------------------
__device__ __forceinline__ float rmax16(float v) {
    v = fmaxf(v, __shfl_xor_sync(0xffffffffu, v, 1));
    v = fmaxf(v, __shfl_xor_sync(0xffffffffu, v, 2));
    v = fmaxf(v, __shfl_xor_sync(0xffffffffu, v, 4));
    v = fmaxf(v, __shfl_xor_sync(0xffffffffu, v, 8));
    return v;
}
__device__ __forceinline__ float rsum16(float v) {
    v += __shfl_xor_sync(0xffffffffu, v, 1);
    v += __shfl_xor_sync(0xffffffffu, v, 2);
    v += __shfl_xor_sync(0xffffffffu, v, 4);
    v += __shfl_xor_sync(0xffffffffu, v, 8);
    return v;
}

__global__ __launch_bounds__(256) void attn_kernel(const int* __restrict__ Qlen,
                                                   const int* __restrict__ Vlen,
                                                   float* __restrict__ out)
{
    extern __shared__ float smn[];
    float (*Qs)[68] = (float(*)[68])smn;               // Qs[d][q], pre-scaled
    float (*Ks)[68] = (float(*)[68])(smn + 64 * 68);   // Ks[d][k]
    float (*Ps)[68] = Ks;                              // Ps[q][k] (aliases Ks)
    float (*Vs)[68] = (float(*)[68])(smn + 2 * 64 * 68); // Vs[k][d]

    const int tid = threadIdx.x;
    const int tx = tid & 15, ty = tid >> 4;
    const int tx4 = tx * 4, ty4 = ty * 4;
    const int q0 = blockIdx.x * 64;
    const int h = blockIdx.y, b = blockIdx.z;
    const int vlen = Vlen[b];
    const int qlen = Qlen[b];

    const float* Qb = g_Q + (size_t)(b * NH + h) * HD * SQL;
    const float* Kb = g_K + (size_t)(b * NH + h) * HD * SKL;
    const float* Vb = g_V + (size_t)b * SKL * DM + h * HD;

    // Q tile, scaled by 1/sqrt(64)
    for (int idx = tid; idx < 64 * 64; idx += 256) {
        int d = idx >> 6, ql = idx & 63;
        Qs[d][ql] = Qb[(size_t)d * SQL + q0 + ql] * 0.125f;
    }

    float acc[4][4];
    float mrow[4], lrow[4];
#pragma unroll
    for (int i = 0; i < 4; i++) {
        mrow[i] = -INFINITY;
        lrow[i] = 0.f;
#pragma unroll
        for (int j = 0; j < 4; j++) acc[i][j] = 0.f;
    }
    __syncthreads();

    for (int k0 = 0; k0 < SKL; k0 += 64) {
        // load K (as [d][k], direct) and V (as [k][d], direct)
        for (int idx = tid; idx < 64 * 16; idx += 256) {
            int r = idx >> 4, c = (idx & 15) * 4;
            *(float4*)&Ks[r][c] = *(const float4*)&Kb[(size_t)r * SKL + k0 + c];
            *(float4*)&Vs[r][c] = *(const float4*)&Vb[(size_t)(k0 + r) * DM + c];
        }
        __syncthreads();

        // S = Q . K^T  (4x4 per thread)
        float s_[4][4];
#pragma unroll
        for (int i = 0; i < 4; i++)
#pragma unroll
            for (int j = 0; j < 4; j++) s_[i][j] = 0.f;

#pragma unroll 8
        for (int d = 0; d < 64; d++) {
            float4 a4 = *(const float4*)&Qs[d][ty4];
            float4 b4 = *(const float4*)&Ks[d][tx4];
            float a[4] = {a4.x, a4.y, a4.z, a4.w};
            float bv[4] = {b4.x, b4.y, b4.z, b4.w};
#pragma unroll
            for (int i = 0; i < 4; i++)
#pragma unroll
                for (int j = 0; j < 4; j++)
                    s_[i][j] = fmaf(a[i], bv[j], s_[i][j]);
        }

        // key mask: subtract 1e12 at global key index == vlen
#pragma unroll
        for (int j = 0; j < 4; j++) {
            if (k0 + tx4 + j == vlen) {
#pragma unroll
                for (int i = 0; i < 4; i++) s_[i][j] -= 1e12f;
            }
        }

        // online softmax update
        float corr[4];
#pragma unroll
        for (int i = 0; i < 4; i++) {
            float tm = fmaxf(fmaxf(s_[i][0], s_[i][1]), fmaxf(s_[i][2], s_[i][3]));
            tm = rmax16(tm);
            float mn = fmaxf(mrow[i], tm);
            corr[i] = __expf(mrow[i] - mn);
            float rs = 0.f;
#pragma unroll
            for (int j = 0; j < 4; j++) {
                s_[i][j] = __expf(s_[i][j] - mn);
                rs += s_[i][j];
            }
            rs = rsum16(rs);
            lrow[i] = lrow[i] * corr[i] + rs;
            mrow[i] = mn;
#pragma unroll
            for (int j = 0; j < 4; j++) acc[i][j] *= corr[i];
        }

        __syncthreads();  // all Ks reads done before Ps overwrite
#pragma unroll
        for (int i = 0; i < 4; i++)
            *(float4*)&Ps[ty4 + i][tx4] =
                make_float4(s_[i][0], s_[i][1], s_[i][2], s_[i][3]);
        __syncthreads();

        // O += P . V
#pragma unroll 4
        for (int k = 0; k < 64; k += 4) {
            float4 pv[4], vv[4];
#pragma unroll
            for (int i = 0; i < 4; i++) pv[i] = *(const float4*)&Ps[ty4 + i][k];
#pragma unroll
            for (int kk = 0; kk < 4; kk++) vv[kk] = *(const float4*)&Vs[k + kk][tx4];
#pragma unroll
            for (int i = 0; i < 4; i++) {
                float p[4] = {pv[i].x, pv[i].y, pv[i].z, pv[i].w};
#pragma unroll
                for (int kk = 0; kk < 4; kk++) {
                    float v[4] = {vv[kk].x, vv[kk].y, vv[kk].z, vv[kk].w};
#pragma unroll
                    for (int j = 0; j < 4; j++)
                        acc[i][j] = fmaf(p[kk], v[j], acc[i][j]);
                }
            }
        }
        __syncthreads();  // before next K/V load overwrites Ks(/Ps) and Vs
    }

    // epilogue: normalize, query mask, write [b][q][h*64+d]
#pragma unroll
    for (int i = 0; i < 4; i++) {
        int q = q0 + ty4 + i;
        float f = (q == qlen) ? 0.f : (1.0f / lrow[i]);
        float4 o = make_float4(acc[i][0] * f, acc[i][1] * f,
                               acc[i][2] * f, acc[i][3] * f);
        *(float4*)&out[(size_t)(b * SQL + q) * DM + h * HD + tx4] = o;
    }
}

extern "C" void kernel_launch(void* const* d_in, const int* in_sizes, int n_in,
                              void* d_out, int out_size)
{
    (void)in_sizes; (void)n_in; (void)out_size;
    const float* Qseq = (const float*)d_in[0];
    const float* Kseq = (const float*)d_in[1];
    const float* Vseq = (const float*)d_in[2];
    const int*   Qlen = (const int*)d_in[3];
    const int*   Vlen = (const int*)d_in[4];
    const float* WQ   = (const float*)d_in[5];
    const float* WK   = (const float*)d_in[6];
    const float* WV   = (const float*)d_in[7];
    float* out = (float*)d_out;

    // 52224 B dynamic smem > 48K default: raise the limit (idempotent, capture-safe)
    cudaFuncSetAttribute(attn_kernel, cudaFuncAttributeMaxDynamicSharedMemorySize,
                         3 * 64 * 68 * (int)sizeof(float));

    dim3 pgrid(BATCH * SQL / 64, NH);
    proj_kernel<<<pgrid, 256>>>(Qseq, WQ, 0);
    proj_kernel<<<pgrid, 256>>>(Kseq, WK, 1);
    proj_kernel<<<pgrid, 256>>>(Vseq, WV, 2);

    dim3 agrid(SQL / 64, NH, BATCH);
    attn_kernel<<<agrid, 256, 3 * 64 * 68 * sizeof(float)>>>(Qlen, Vlen, out);
}

// round 12
// speedup vs baseline: 1.4004x; 1.4004x over previous
#include <cuda_runtime.h>
#include <cuda_bf16.h>
#include <math.h>
#include <stdint.h>

#define BATCH 4
#define SQL 2048
#define SKL 2048
#define DM 1024
#define NH 16
#define HD 64

// Scratch: projected Q/K in [b][h][d][s], V in [b][s][n]
__device__ float g_Q[(size_t)BATCH * NH * HD * SQL];
__device__ float g_K[(size_t)BATCH * NH * HD * SKL];
__device__ float g_V[(size_t)BATCH * SKL * DM];

// bf16 hi/lo split scratch: X per projection [8192][1024], W^T [n=1024][k=1024]
#define XN ((size_t)8192 * 1024)
#define WN ((size_t)1024 * 1024)
__device__ __align__(16) __nv_bfloat16 g_Xhi[3 * XN];
__device__ __align__(16) __nv_bfloat16 g_Xlo[3 * XN];
__device__ __align__(16) __nv_bfloat16 g_Wthi[3 * WN];
__device__ __align__(16) __nv_bfloat16 g_Wtlo[3 * WN];

__device__ __forceinline__ uint32_t smem_u32(const void* p) {
    uint32_t a;
    asm("{ .reg .u64 t; cvta.to.shared.u64 t, %1; cvt.u32.u64 %0, t; }" : "=r"(a) : "l"(p));
    return a;
}
__device__ __forceinline__ void ldsm_x4(uint32_t* r, uint32_t addr) {
    asm volatile("ldmatrix.sync.aligned.m8n8.x4.shared.b16 {%0,%1,%2,%3}, [%4];"
                 : "=r"(r[0]), "=r"(r[1]), "=r"(r[2]), "=r"(r[3]) : "r"(addr));
}
__device__ __forceinline__ void mma16816(float* d, const uint32_t* a, const uint32_t* b) {
    asm volatile(
        "mma.sync.aligned.m16n8k16.row.col.f32.bf16.bf16.f32 "
        "{%0,%1,%2,%3}, {%4,%5,%6,%7}, {%8,%9}, {%0,%1,%2,%3};"
        : "+f"(d[0]), "+f"(d[1]), "+f"(d[2]), "+f"(d[3])
        : "r"(a[0]), "r"(a[1]), "r"(a[2]), "r"(a[3]), "r"(b[0]), "r"(b[1]));
}
__device__ __forceinline__ void bf16_split(float v, __nv_bfloat16& h, __nv_bfloat16& l) {
    h = __float2bfloat16_rn(v);
    l = __float2bfloat16_rn(v - __bfloat162float(h));
}

// ---------------------------------------------------------------------------
// Convert X [8192][1024] fp32 -> bf16 hi/lo (same layout).
// ---------------------------------------------------------------------------
__global__ __launch_bounds__(256) void conv_x_kernel(const float* __restrict__ X,
                                                     __nv_bfloat16* __restrict__ hi,
                                                     __nv_bfloat16* __restrict__ lo)
{
    size_t i = ((size_t)blockIdx.x * 256 + threadIdx.x) * 4;
    float4 v = *(const float4*)(X + i);
    float vv[4] = {v.x, v.y, v.z, v.w};
    unsigned short hp[4], lp[4];
#pragma unroll
    for (int j = 0; j < 4; j++) {
        __nv_bfloat16 h, l;
        bf16_split(vv[j], h, l);
        hp[j] = __bfloat16_as_ushort(h);
        lp[j] = __bfloat16_as_ushort(l);
    }
    *(uint2*)(hi + i) = make_uint2((uint32_t)hp[0] | ((uint32_t)hp[1] << 16),
                                   (uint32_t)hp[2] | ((uint32_t)hp[3] << 16));
    *(uint2*)(lo + i) = make_uint2((uint32_t)lp[0] | ((uint32_t)lp[1] << 16),
                                   (uint32_t)lp[2] | ((uint32_t)lp[3] << 16));
}

// ---------------------------------------------------------------------------
// Convert + transpose W [k][n] fp32 -> Wt hi/lo [n][k] bf16.
// ---------------------------------------------------------------------------
__global__ __launch_bounds__(256) void conv_w_kernel(const float* __restrict__ W,
                                                     __nv_bfloat16* __restrict__ Whi,
                                                     __nv_bfloat16* __restrict__ Wlo)
{
    __shared__ float t[32][33];
    const int k0 = blockIdx.x * 32, n0 = blockIdx.y * 32;
    const int tx = threadIdx.x, ty = threadIdx.y;
    for (int i = ty; i < 32; i += 8)
        t[i][tx] = W[(size_t)(k0 + i) * DM + n0 + tx];
    __syncthreads();
    for (int i = ty; i < 32; i += 8) {
        float v = t[tx][i];                 // = W[k0+tx][n0+i]
        __nv_bfloat16 h, l;
        bf16_split(v, h, l);
        Whi[(size_t)(n0 + i) * DM + k0 + tx] = h;
        Wlo[(size_t)(n0 + i) * DM + k0 + tx] = l;
    }
}

// ---------------------------------------------------------------------------
// Projection GEMM on mma.sync (bf16x3 compensated, fp32 accum).
// CTA tile M=128, N=64 (one head), K=1024 in 16 chunks of 64.
// 8 warps: warpM = wid&3 (32 rows), warpN = wid>>2 (32 cols).
// smem rows padded to 72 bf16 (144 B) -> conflict-free ldmatrix phases.
// grid = (64, 16 heads, 3 projections).
// ---------------------------------------------------------------------------
#define SA_HI 0
#define SA_LO (128 * 72)
#define SB_HI (2 * 128 * 72)
#define SB_LO (2 * 128 * 72 + 64 * 72)
#define PROJ_SMEM ((2 * 128 * 72 + 2 * 64 * 72) * 2)   // 55296 B

__global__ __launch_bounds__(256) void proj_mma_kernel()
{
    extern __shared__ __nv_bfloat16 sb[];
    const int tid = threadIdx.x;
    const int wid = tid >> 5, lane = tid & 31;
    const int m0 = blockIdx.x * 128;
    const int h = blockIdx.y;
    const int n0 = h * 64;
    const int z = blockIdx.z;
    const int warpM = wid & 3, warpN = wid >> 2;

    const __nv_bfloat16* Xhi = g_Xhi + (size_t)z * XN;
    const __nv_bfloat16* Xlo = g_Xlo + (size_t)z * XN;
    const __nv_bfloat16* Whi = g_Wthi + (size_t)z * WN;
    const __nv_bfloat16* Wlo = g_Wtlo + (size_t)z * WN;

    float acc[2][4][4];
#pragma unroll
    for (int i = 0; i < 2; i++)
#pragma unroll
        for (int j = 0; j < 4; j++)
#pragma unroll
            for (int r = 0; r < 4; r++) acc[i][j][r] = 0.f;

    const uint32_t smb = smem_u32(sb);
    // per-lane ldmatrix address components (byte offsets)
    const uint32_t aRowOff = (uint32_t)(warpM * 32 + (lane & 15)) * 144 + ((lane >> 4) * 16);
    const uint32_t bRowOff = (uint32_t)(warpN * 32 + ((lane >> 4) * 8) + (lane & 7)) * 144
                             + (((lane >> 3) & 1) * 16);
    const uint32_t aHiB = smb + SA_HI * 2, aLoB = smb + SA_LO * 2;
    const uint32_t bHiB = smb + SB_HI * 2, bLoB = smb + SB_LO * 2;

    for (int c = 0; c < 16; c++) {
        const int k0 = c * 64;
        __syncthreads();   // previous iteration's reads complete before overwrite

        // A tiles: 128 rows x 64 k, hi+lo (uint4 = 8 bf16)
#pragma unroll
        for (int it = 0; it < 4; it++) {
            int task = it * 256 + tid;
            int r = task >> 3, cc = task & 7;
            const size_t g = (size_t)(m0 + r) * DM + k0 + cc * 8;
            *(uint4*)(sb + SA_HI + r * 72 + cc * 8) = *(const uint4*)(Xhi + g);
            *(uint4*)(sb + SA_LO + r * 72 + cc * 8) = *(const uint4*)(Xlo + g);
        }
        // B tiles: 64 n-rows x 64 k, hi+lo
#pragma unroll
        for (int it = 0; it < 2; it++) {
            int task = it * 256 + tid;
            int r = task >> 3, cc = task & 7;
            const size_t g = (size_t)(n0 + r) * DM + k0 + cc * 8;
            *(uint4*)(sb + SB_HI + r * 72 + cc * 8) = *(const uint4*)(Whi + g);
            *(uint4*)(sb + SB_LO + r * 72 + cc * 8) = *(const uint4*)(Wlo + g);
        }
        __syncthreads();

#pragma unroll
        for (int ks = 0; ks < 4; ks++) {
            const uint32_t kb = ks * 32;
            uint32_t ah[2][4], al[2][4], bh[4][2], bl[4][2], t4[4];
#pragma unroll
            for (int mi = 0; mi < 2; mi++) {
                ldsm_x4(ah[mi], aHiB + aRowOff + mi * 16 * 144 + kb);
                ldsm_x4(al[mi], aLoB + aRowOff + mi * 16 * 144 + kb);
            }
#pragma unroll
            for (int p = 0; p < 2; p++) {
                ldsm_x4(t4, bHiB + bRowOff + p * 16 * 144 + kb);
                bh[2*p][0] = t4[0]; bh[2*p][1] = t4[1];
                bh[2*p+1][0] = t4[2]; bh[2*p+1][1] = t4[3];
                ldsm_x4(t4, bLoB + bRowOff + p * 16 * 144 + kb);
                bl[2*p][0] = t4[0]; bl[2*p][1] = t4[1];
                bl[2*p+1][0] = t4[2]; bl[2*p+1][1] = t4[3];
            }
#pragma unroll
            for (int mi = 0; mi < 2; mi++)
#pragma unroll
                for (int ni = 0; ni < 4; ni++) {
                    mma16816(acc[mi][ni], ah[mi], bh[ni]);
                    mma16816(acc[mi][ni], ah[mi], bl[ni]);
                    mma16816(acc[mi][ni], al[mi], bh[ni]);
                }
        }
    }

    // Epilogue. D frag: d0,d1 at (row=lane/4, col=(lane%4)*2+{0,1}); d2,d3 at row+8.
    const int r0 = lane >> 2, c0 = (lane & 3) * 2;
    const int bb = m0 >> 11, s0 = m0 & 2047;
#pragma unroll
    for (int mi = 0; mi < 2; mi++)
#pragma unroll
        for (int ni = 0; ni < 4; ni++) {
            int lm = warpM * 32 + mi * 16 + r0;       // local row 0..127
            int ln = warpN * 32 + ni * 8 + c0;        // local col 0..63
            if (z == 2) {
                float* o = &g_V[(size_t)(m0 + lm) * DM + n0 + ln];
                *(float2*)o = make_float2(acc[mi][ni][0], acc[mi][ni][1]);
                *(float2*)(o + 8 * DM) = make_float2(acc[mi][ni][2], acc[mi][ni][3]);
            } else {
                float* outp = (z == 0) ? g_Q : g_K;
                const size_t base = ((size_t)(bb * NH + h) * HD) * SQL + s0;
                outp[base + (size_t)ln * SQL + lm] = acc[mi][ni][0];
                outp[base + (size_t)(ln + 1) * SQL + lm] = acc[mi][ni][1];
                outp[base + (size_t)ln * SQL + lm + 8] = acc[mi][ni][2];
                outp[base + (size_t)(ln + 1) * SQL + lm + 8] = acc[mi][ni][3];
            }
        }
}

// ---------------------------------------------------------------------------
// Flash attention (unchanged, verified rel_err 1.4e-6).
// ---------------------------------------------------------------------------
__device__ __forceinline__ float rmax16(float v) {
    v = fmaxf(v, __shfl_xor_sync(0xffffffffu, v, 1));
    v = fmaxf(v, __shfl_xor_sync(0xffffffffu, v, 2));
    v = fmaxf(v, __shfl_xor_sync(0xffffffffu, v, 4));
    v = fmaxf(v, __shfl_xor_sync(0xffffffffu, v, 8));
    return v;
}
__device__ __forceinline__ float rsum16(float v) {
    v += __shfl_xor_sync(0xffffffffu, v, 1);
    v += __shfl_xor_sync(0xffffffffu, v, 2);
    v += __shfl_xor_sync(0xffffffffu, v, 4);
    v += __shfl_xor_sync(0xffffffffu, v, 8);
    return v;
}

__global__ __launch_bounds__(256) void attn_kernel(const int* __restrict__ Qlen,
                                                   const int* __restrict__ Vlen,
                                                   float* __restrict__ out)
{
    extern __shared__ float smn[];
    float (*Qs)[68] = (float(*)[68])smn;
    float (*Ks)[68] = (float(*)[68])(smn + 64 * 68);
    float (*Ps)[68] = Ks;
    float (*Vs)[68] = (float(*)[68])(smn + 2 * 64 * 68);

    const int tid = threadIdx.x;
    const int tx = tid & 15, ty = tid >> 4;
    const int tx4 = tx * 4, ty4 = ty * 4;
    const int q0 = blockIdx.x * 64;
    const int h = blockIdx.y, b = blockIdx.z;
    const int vlen = Vlen[b];
    const int qlen = Qlen[b];

    const float* Qb = g_Q + (size_t)(b * NH + h) * HD * SQL;
    const float* Kb = g_K + (size_t)(b * NH + h) * HD * SKL;
    const float* Vb = g_V + (size_t)b * SKL * DM + h * HD;

    for (int idx = tid; idx < 64 * 64; idx += 256) {
        int d = idx >> 6, ql = idx & 63;
        Qs[d][ql] = Qb[(size_t)d * SQL + q0 + ql] * 0.125f;
    }

    float acc[4][4];
    float mrow[4], lrow[4];
#pragma unroll
    for (int i = 0; i < 4; i++) {
        mrow[i] = -INFINITY;
        lrow[i] = 0.f;
#pragma unroll
        for (int j = 0; j < 4; j++) acc[i][j] = 0.f;
    }
    __syncthreads();

    for (int k0 = 0; k0 < SKL; k0 += 64) {
        for (int idx = tid; idx < 64 * 16; idx += 256) {
            int r = idx >> 4, c = (idx & 15) * 4;
            *(float4*)&Ks[r][c] = *(const float4*)&Kb[(size_t)r * SKL + k0 + c];
            *(float4*)&Vs[r][c] = *(const float4*)&Vb[(size_t)(k0 + r) * DM + c];
        }
        __syncthreads();

        float s_[4][4];
#pragma unroll
        for (int i = 0; i < 4; i++)
#pragma unroll
            for (int j = 0; j < 4; j++) s_[i][j] = 0.f;

#pragma unroll 8
        for (int d = 0; d < 64; d++) {
            float4 a4 = *(const float4*)&Qs[d][ty4];
            float4 b4 = *(const float4*)&Ks[d][tx4];
            float a[4] = {a4.x, a4.y, a4.z, a4.w};
            float bv[4] = {b4.x, b4.y, b4.z, b4.w};
#pragma unroll
            for (int i = 0; i < 4; i++)
#pragma unroll
                for (int j = 0; j < 4; j++)
                    s_[i][j] = fmaf(a[i], bv[j], s_[i][j]);
        }

#pragma unroll
        for (int j = 0; j < 4; j++) {
            if (k0 + tx4 + j == vlen) {
#pragma unroll
                for (int i = 0; i < 4; i++) s_[i][j] -= 1e12f;
            }
        }

        float corr[4];
#pragma unroll
        for (int i = 0; i < 4; i++) {
            float tm = fmaxf(fmaxf(s_[i][0], s_[i][1]), fmaxf(s_[i][2], s_[i][3]));
            tm = rmax16(tm);
            float mn = fmaxf(mrow[i], tm);
            corr[i] = __expf(mrow[i] - mn);
            float rs = 0.f;
#pragma unroll
            for (int j = 0; j < 4; j++) {
                s_[i][j] = __expf(s_[i][j] - mn);
                rs += s_[i][j];
            }
            rs = rsum16(rs);
            lrow[i] = lrow[i] * corr[i] + rs;
            mrow[i] = mn;
#pragma unroll
            for (int j = 0; j < 4; j++) acc[i][j] *= corr[i];
        }

        __syncthreads();
#pragma unroll
        for (int i = 0; i < 4; i++)
            *(float4*)&Ps[ty4 + i][tx4] =
                make_float4(s_[i][0], s_[i][1], s_[i][2], s_[i][3]);
        __syncthreads();

#pragma unroll 4
        for (int k = 0; k < 64; k += 4) {
            float4 pv[4], vv[4];
#pragma unroll
            for (int i = 0; i < 4; i++) pv[i] = *(const float4*)&Ps[ty4 + i][k];
#pragma unroll
            for (int kk = 0; kk < 4; kk++) vv[kk] = *(const float4*)&Vs[k + kk][tx4];
#pragma unroll
            for (int i = 0; i < 4; i++) {
                float p[4] = {pv[i].x, pv[i].y, pv[i].z, pv[i].w};
#pragma unroll
                for (int kk = 0; kk < 4; kk++) {
                    float v[4] = {vv[kk].x, vv[kk].y, vv[kk].z, vv[kk].w};
#pragma unroll
                    for (int j = 0; j < 4; j++)
                        acc[i][j] = fmaf(p[kk], v[j], acc[i][j]);
                }
            }
        }
        __syncthreads();
    }

#pragma unroll
    for (int i = 0; i < 4; i++) {
        int q = q0 + ty4 + i;
        float f = (q == qlen) ? 0.f : (1.0f / lrow[i]);
        float4 o = make_float4(acc[i][0] * f, acc[i][1] * f,
                               acc[i][2] * f, acc[i][3] * f);
        *(float4*)&out[(size_t)(b * SQL + q) * DM + h * HD + tx4] = o;
    }
}

extern "C" void kernel_launch(void* const* d_in, const int* in_sizes, int n_in,
                              void* d_out, int out_size)
{
    (void)in_sizes; (void)n_in; (void)out_size;
    const float* Qseq = (const float*)d_in[0];
    const float* Kseq = (const float*)d_in[1];
    const float* Vseq = (const float*)d_in[2];
    const int*   Qlen = (const int*)d_in[3];
    const int*   Vlen = (const int*)d_in[4];
    const float* WQ   = (const float*)d_in[5];
    const float* WK   = (const float*)d_in[6];
    const float* WV   = (const float*)d_in[7];
    float* out = (float*)d_out;

    cudaFuncSetAttribute(proj_mma_kernel, cudaFuncAttributeMaxDynamicSharedMemorySize, PROJ_SMEM);
    cudaFuncSetAttribute(attn_kernel, cudaFuncAttributeMaxDynamicSharedMemorySize,
                         3 * 64 * 68 * (int)sizeof(float));

    // resolve device-scratch addresses (host-side, capture-safe: no allocs)
    __nv_bfloat16 *xhi, *xlo, *whi, *wlo;
    cudaGetSymbolAddress((void**)&xhi, g_Xhi);
    cudaGetSymbolAddress((void**)&xlo, g_Xlo);
    cudaGetSymbolAddress((void**)&whi, g_Wthi);
    cudaGetSymbolAddress((void**)&wlo, g_Wtlo);

    conv_x_kernel<<<8192, 256>>>(Qseq, xhi + 0 * XN, xlo + 0 * XN);
    conv_x_kernel<<<8192, 256>>>(Kseq, xhi + 1 * XN, xlo + 1 * XN);
    conv_x_kernel<<<8192, 256>>>(Vseq, xhi + 2 * XN, xlo + 2 * XN);
    conv_w_kernel<<<dim3(32, 32), dim3(32, 8)>>>(WQ, whi + 0 * WN, wlo + 0 * WN);
    conv_w_kernel<<<dim3(32, 32), dim3(32, 8)>>>(WK, whi + 1 * WN, wlo + 1 * WN);
    conv_w_kernel<<<dim3(32, 32), dim3(32, 8)>>>(WV, whi + 2 * WN, wlo + 2 * WN);

    proj_mma_kernel<<<dim3(BATCH * SQL / 128, NH, 3), 256, PROJ_SMEM>>>();

    dim3 agrid(SQL / 64, NH, BATCH);
    attn_kernel<<<agrid, 256, 3 * 64 * 68 * sizeof(float)>>>(Qlen, Vlen, out);
}